// round 11
// baseline (speedup 1.0000x reference)
#include <cuda_runtime.h>
#include <cuda_fp16.h>
#include <mma.h>
#include <math.h>
#include <stdint.h>

using namespace nvcuda;

#define BSZ 4
#define TN  2048
#define CN  1024
#define HN  1024

// fp32 scratch
__device__ float g_S[BSZ * TN * TN];
// fp16 scratch
__device__ __half g_Xh[BSZ * TN * CN];
__device__ __half g_Wh[3][CN * HN];
__device__ __half g_Qh[BSZ * TN * HN];
__device__ __half g_Kh[BSZ * TN * HN];
__device__ __half g_Vh[BSZ * TN * HN];
__device__ __half g_Ph[BSZ * TN * TN];

// ---------------------------------------------------------------------------
__device__ __forceinline__ uint32_t smem_u32(const void* p) {
    uint32_t a;
    asm("{ .reg .u64 t; cvta.to.shared.u64 t, %1; cvt.u32.u64 %0, t; }" : "=r"(a) : "l"(p));
    return a;
}
#define CP_ASYNC16(dst_u32, src_ptr) \
    asm volatile("cp.async.cg.shared.global [%0], [%1], 16;" :: "r"(dst_u32), "l"(src_ptr))
#define CP_COMMIT() asm volatile("cp.async.commit_group;" ::: "memory")
#define CP_WAIT(N)  asm volatile("cp.async.wait_group %0;" :: "n"(N) : "memory")

// ---------------------------------------------------------------------------
// fp16 tile: BM=BN=128, BK=64. 8 warps (4x2), warp=32x64, wmma m16n16k16.
// A smem [128][72] halves; B_KN smem [64][136]; B_NK smem [128][72].
// Fragments double-buffered across ks steps (LDSM latency hidden by HMMA).
// ---------------------------------------------------------------------------
#define A_LDH 72
#define B_LDH_KN 136
#define ABUF_BYTES (128 * A_LDH * 2)          // 18432
#define BUF_STRIDE (2 * ABUF_BYTES)           // 36864
#define SMEM_BYTES (2 * BUF_STRIDE)           // 73728
#define STG_LD 132                            // fp32 staging ld (epilogue)

template <bool B_KN, bool OUT_HALF>
__device__ __forceinline__ void wmma_tile_h(
    const __half* __restrict__ A, int lda,
    const __half* __restrict__ B, int ldb,
    float* __restrict__ Cf, __half* __restrict__ Ch, int ldc,
    int kChunks, int br, int bc, float scale)
{
    extern __shared__ char smc[];
    const uint32_t sm_b = smem_u32(smc);
    const int tid = threadIdx.x;
    const int wid = tid >> 5;
    const int wr = wid >> 1;     // 0..3
    const int wc = wid & 1;      // 0..1

    const __half* AsH[2] = { (const __half*)smc,
                             (const __half*)(smc + BUF_STRIDE) };
    const __half* BsH[2] = { (const __half*)(smc + ABUF_BYTES),
                             (const __half*)(smc + BUF_STRIDE + ABUF_BYTES) };
    const uint32_t AsU[2] = { sm_b, sm_b + BUF_STRIDE };
    const uint32_t BsU[2] = { sm_b + ABUF_BYTES, sm_b + BUF_STRIDE + ABUF_BYTES };

    wmma::fragment<wmma::accumulator, 16, 16, 16, float> acc[2][4];
#pragma unroll
    for (int i = 0; i < 2; i++)
#pragma unroll
        for (int j = 0; j < 4; j++) wmma::fill_fragment(acc[i][j], 0.0f);

    auto issue_load = [&](int b, int kc) {
#pragma unroll
        for (int p = 0; p < 4; ++p) {
            int idx = p * 256 + tid;
            int row = idx >> 3, c8 = idx & 7;
            CP_ASYNC16(AsU[b] + (row * A_LDH + c8 * 8) * 2,
                       A + (size_t)(br * 128 + row) * lda + kc * 64 + c8 * 8);
        }
        if (B_KN) {
#pragma unroll
            for (int p = 0; p < 4; ++p) {
                int idx = p * 256 + tid;
                int row = idx >> 4, c8 = idx & 15;
                CP_ASYNC16(BsU[b] + (row * B_LDH_KN + c8 * 8) * 2,
                           B + (size_t)(kc * 64 + row) * ldb + bc * 128 + c8 * 8);
            }
        } else {
#pragma unroll
            for (int p = 0; p < 4; ++p) {
                int idx = p * 256 + tid;
                int row = idx >> 3, c8 = idx & 7;
                CP_ASYNC16(BsU[b] + (row * A_LDH + c8 * 8) * 2,
                           B + (size_t)(bc * 128 + row) * ldb + kc * 64 + c8 * 8);
            }
        }
        CP_COMMIT();
    };

    issue_load(0, 0);

    // fragment double buffers
    wmma::fragment<wmma::matrix_a, 16, 16, 16, __half, wmma::row_major> af[2][2];
    wmma::fragment<wmma::matrix_b, 16, 16, 16, __half, wmma::row_major> bfr[2][4];
    wmma::fragment<wmma::matrix_b, 16, 16, 16, __half, wmma::col_major> bfc[2][4];

    auto load_frags = [&](int slot, const __half* Asb, const __half* Bsb, int ks) {
        const int k0 = ks * 16;
#pragma unroll
        for (int i = 0; i < 2; i++)
            wmma::load_matrix_sync(af[slot][i], Asb + (wr * 32 + i * 16) * A_LDH + k0, A_LDH);
        if (B_KN) {
#pragma unroll
            for (int j = 0; j < 4; j++)
                wmma::load_matrix_sync(bfr[slot][j], Bsb + k0 * B_LDH_KN + wc * 64 + j * 16, B_LDH_KN);
        } else {
#pragma unroll
            for (int j = 0; j < 4; j++)
                wmma::load_matrix_sync(bfc[slot][j], Bsb + (wc * 64 + j * 16) * A_LDH + k0, A_LDH);
        }
    };
    auto do_mma = [&](int slot) {
        if (B_KN) {
#pragma unroll
            for (int i = 0; i < 2; i++)
#pragma unroll
                for (int j = 0; j < 4; j++)
                    wmma::mma_sync(acc[i][j], af[slot][i], bfr[slot][j], acc[i][j]);
        } else {
#pragma unroll
            for (int i = 0; i < 2; i++)
#pragma unroll
                for (int j = 0; j < 4; j++)
                    wmma::mma_sync(acc[i][j], af[slot][i], bfc[slot][j], acc[i][j]);
        }
    };

    int cur = 0;
    for (int kc = 0; kc < kChunks; ++kc) {
        if (kc + 1 < kChunks) { issue_load(cur ^ 1, kc + 1); CP_WAIT(1); }
        else                  { CP_WAIT(0); }
        __syncthreads();

        const __half* Asb = AsH[cur];
        const __half* Bsb = BsH[cur];
        load_frags(0, Asb, Bsb, 0);
        int slot = 0;
#pragma unroll
        for (int ks = 0; ks < 4; ++ks) {
            if (ks < 3) load_frags(slot ^ 1, Asb, Bsb, ks + 1);
            do_mma(slot);
            slot ^= 1;
        }
        __syncthreads();
        cur ^= 1;
    }

    if (!OUT_HALF) {
#pragma unroll
        for (int i = 0; i < 2; i++)
#pragma unroll
            for (int j = 0; j < 4; j++) {
#pragma unroll
                for (int t = 0; t < acc[i][j].num_elements; t++) acc[i][j].x[t] *= scale;
                float* cp = Cf + (size_t)(br * 128 + wr * 32 + i * 16) * ldc + bc * 128 + wc * 64 + j * 16;
                wmma::store_matrix_sync(cp, acc[i][j], ldc, wmma::mem_row_major);
            }
    } else {
        float* stg = (float*)smc;
#pragma unroll
        for (int i = 0; i < 2; i++)
#pragma unroll
            for (int j = 0; j < 4; j++)
                wmma::store_matrix_sync(stg + (size_t)(wr * 32 + i * 16) * STG_LD + wc * 64 + j * 16,
                                        acc[i][j], STG_LD, wmma::mem_row_major);
        __syncthreads();
        const int row = tid >> 1;
        const int cb = (tid & 1) * 64;
        const float* srow = stg + (size_t)row * STG_LD + cb;
        __half2* drow = (__half2*)(Ch + (size_t)(br * 128 + row) * ldc + bc * 128 + cb);
#pragma unroll
        for (int c = 0; c < 32; ++c)
            drow[c] = __floats2half2_rn(srow[2 * c], srow[2 * c + 1]);
    }
}

// ---------------------------------------------------------------------------
// Kernel 0: fused fp32 -> fp16 conversion. grid.y: 0=X, 1..3=W[q,k,v]
// ---------------------------------------------------------------------------
__global__ void __launch_bounds__(256)
f2h_all(const float* __restrict__ x, const float* __restrict__ wq,
        const float* __restrict__ wk, const float* __restrict__ wv)
{
    const int z = blockIdx.y;
    const float* s;
    __half* d;
    int n4;
    if (z == 0) { s = x;  d = g_Xh;    n4 = BSZ * TN * CN / 4; }
    else {
        n4 = CN * HN / 4;
        if (z == 1)      { s = wq; d = g_Wh[0]; }
        else if (z == 2) { s = wk; d = g_Wh[1]; }
        else             { s = wv; d = g_Wh[2]; }
    }
    int i = blockIdx.x * 256 + threadIdx.x;
    if (i < n4) {
        float4 v = *(const float4*)(s + (size_t)i * 4);
        __half2* o = (__half2*)(d + (size_t)i * 4);
        o[0] = __floats2half2_rn(v.x, v.y);
        o[1] = __floats2half2_rn(v.z, v.w);
    }
}

// ---------------------------------------------------------------------------
// Kernel 1: QKV projections. grid = (8, 64, 3). Wh = [C,H] -> B_KN, out half
// ---------------------------------------------------------------------------
__global__ void __launch_bounds__(256, 2)
qkv_h()
{
    __half* Out;
    if (blockIdx.z == 0)      Out = g_Qh;
    else if (blockIdx.z == 1) Out = g_Kh;
    else                      Out = g_Vh;
    wmma_tile_h<true, true>(g_Xh, CN, g_Wh[blockIdx.z], HN,
                            nullptr, Out, HN, CN / 64, blockIdx.y, blockIdx.x, 1.0f);
}

// ---------------------------------------------------------------------------
// Kernel 2: S = Qh Kh^T * scale, causal block skip. grid = (16,16,BSZ). B_NK
// ---------------------------------------------------------------------------
__global__ void __launch_bounds__(256, 2)
scores_h()
{
    if (blockIdx.x > blockIdx.y) return;
    const int b = blockIdx.z;
    const __half* Q = g_Qh + (size_t)b * TN * HN;
    const __half* K = g_Kh + (size_t)b * TN * HN;
    float* S = g_S + (size_t)b * TN * TN;
    wmma_tile_h<false, false>(Q, HN, K, HN, S, nullptr, TN, HN / 64,
                              blockIdx.y, blockIdx.x, 0.03125f);
}

// ---------------------------------------------------------------------------
// Kernel 3: causal softmax; reads fp32 S, writes fp16 P (padded). grid (TN,BSZ)
// ---------------------------------------------------------------------------
__global__ void __launch_bounds__(256)
softmax_h()
{
    const int t = blockIdx.x;
    const int b = blockIdx.y;
    const float* row = g_S + ((size_t)b * TN + t) * TN;
    __half* prow = g_Ph + ((size_t)b * TN + t) * TN;
    const int n = t + 1;
    const int tid = threadIdx.x;

    __shared__ float red[8];

    float m = -INFINITY;
    for (int i = tid; i < n; i += 256) m = fmaxf(m, row[i]);
#pragma unroll
    for (int o = 16; o > 0; o >>= 1) m = fmaxf(m, __shfl_xor_sync(0xffffffffu, m, o));
    if ((tid & 31) == 0) red[tid >> 5] = m;
    __syncthreads();
    m = -INFINITY;
#pragma unroll
    for (int w = 0; w < 8; w++) m = fmaxf(m, red[w]);
    __syncthreads();

    float s = 0.f;
    for (int i = tid; i < n; i += 256) s += expf(row[i] - m);
#pragma unroll
    for (int o = 16; o > 0; o >>= 1) s += __shfl_xor_sync(0xffffffffu, s, o);
    if ((tid & 31) == 0) red[tid >> 5] = s;
    __syncthreads();
    s = 0.f;
#pragma unroll
    for (int w = 0; w < 8; w++) s += red[w];

    const float inv = 1.0f / s;
    for (int i = tid; i < n; i += 256) prow[i] = __float2half(expf(row[i] - m) * inv);

    const int npad = ((t >> 7) + 1) << 7;
    for (int i = n + tid; i < npad; i += 256) prow[i] = __float2half(0.f);
}

// ---------------------------------------------------------------------------
// Kernel 4: O = Ph Vh, k truncated at diagonal. grid (8,16,BSZ). B_KN, fp32 out
// ---------------------------------------------------------------------------
__global__ void __launch_bounds__(256, 2)
pv_h(float* __restrict__ out)
{
    const int b = blockIdx.z;
    const __half* P = g_Ph + (size_t)b * TN * TN;
    const __half* V = g_Vh + (size_t)b * TN * HN;
    float* O = out + (size_t)b * TN * HN;
    const int kChunks = (blockIdx.y + 1) * 2;   // (br+1)*128 / 64
    wmma_tile_h<true, false>(P, TN, V, HN, O, nullptr, HN, kChunks,
                             blockIdx.y, blockIdx.x, 1.0f);
}

// ---------------------------------------------------------------------------
extern "C" void kernel_launch(void* const* d_in, const int* in_sizes, int n_in,
                              void* d_out, int out_size)
{
    const float* x  = (const float*)d_in[0];
    const float* Wk = (const float*)d_in[1];
    const float* Wq = (const float*)d_in[2];
    const float* Wv = (const float*)d_in[3];
    float* out = (float*)d_out;

    cudaFuncSetAttribute(qkv_h,    cudaFuncAttributeMaxDynamicSharedMemorySize, SMEM_BYTES);
    cudaFuncSetAttribute(scores_h, cudaFuncAttributeMaxDynamicSharedMemorySize, SMEM_BYTES);
    cudaFuncSetAttribute(pv_h,     cudaFuncAttributeMaxDynamicSharedMemorySize, SMEM_BYTES);

    const int nX4 = BSZ * TN * CN / 4;
    f2h_all<<<dim3((nX4 + 255) / 256, 4), 256>>>(x, Wq, Wk, Wv);

    qkv_h<<<dim3(HN / 128, (BSZ * TN) / 128, 3), 256, SMEM_BYTES>>>();
    scores_h<<<dim3(TN / 128, TN / 128, BSZ), 256, SMEM_BYTES>>>();
    softmax_h<<<dim3(TN, BSZ), 256>>>();
    pv_h<<<dim3(HN / 128, TN / 128, BSZ), 256, SMEM_BYTES>>>(out);
}

// round 16
// speedup vs baseline: 1.0377x; 1.0377x over previous
#include <cuda_runtime.h>
#include <cuda_fp16.h>
#include <mma.h>
#include <math.h>
#include <stdint.h>

using namespace nvcuda;

#define BSZ 4
#define TN  2048
#define CN  1024
#define HN  1024

// fp32 scratch
__device__ float g_S[BSZ * TN * TN];
// fp16 scratch
__device__ __half g_Xh[BSZ * TN * CN];
__device__ __half g_Wh[3][CN * HN];
__device__ __half g_Qh[BSZ * TN * HN];
__device__ __half g_Kh[BSZ * TN * HN];
__device__ __half g_Vh[BSZ * TN * HN];
__device__ __half g_Ph[BSZ * TN * TN];

// ---------------------------------------------------------------------------
__device__ __forceinline__ uint32_t smem_u32(const void* p) {
    uint32_t a;
    asm("{ .reg .u64 t; cvta.to.shared.u64 t, %1; cvt.u32.u64 %0, t; }" : "=r"(a) : "l"(p));
    return a;
}
#define CP_ASYNC16(dst_u32, src_ptr) \
    asm volatile("cp.async.cg.shared.global [%0], [%1], 16;" :: "r"(dst_u32), "l"(src_ptr))
#define CP_COMMIT() asm volatile("cp.async.commit_group;" ::: "memory")
#define CP_WAIT(N)  asm volatile("cp.async.wait_group %0;" :: "n"(N) : "memory")

// ---------------------------------------------------------------------------
// fp16 tile: BM=BN=128, BK=64. 8 warps (4x2), warp=32x64, wmma m16n16k16.
// A smem [128][72] halves; B_KN smem [64][136]; B_NK smem [128][72].
// ---------------------------------------------------------------------------
#define A_LDH 72
#define B_LDH_KN 136
#define ABUF_BYTES (128 * A_LDH * 2)          // 18432
#define BUF_STRIDE (2 * ABUF_BYTES)           // 36864
#define SMEM_BYTES (2 * BUF_STRIDE)           // 73728
#define STG_LD 132                            // fp32 staging ld (epilogue)

template <bool B_KN, bool OUT_HALF>
__device__ __forceinline__ void wmma_tile_h(
    const __half* __restrict__ A, int lda,
    const __half* __restrict__ B, int ldb,
    float* __restrict__ Cf, __half* __restrict__ Ch, int ldc,
    int kChunks, int br, int bc, float scale)
{
    extern __shared__ char smc[];
    const uint32_t sm_b = smem_u32(smc);
    const int tid = threadIdx.x;
    const int wid = tid >> 5;
    const int wr = wid >> 1;     // 0..3
    const int wc = wid & 1;      // 0..1

    const __half* AsH[2] = { (const __half*)smc,
                             (const __half*)(smc + BUF_STRIDE) };
    const __half* BsH[2] = { (const __half*)(smc + ABUF_BYTES),
                             (const __half*)(smc + BUF_STRIDE + ABUF_BYTES) };
    const uint32_t AsU[2] = { sm_b, sm_b + BUF_STRIDE };
    const uint32_t BsU[2] = { sm_b + ABUF_BYTES, sm_b + BUF_STRIDE + ABUF_BYTES };

    wmma::fragment<wmma::accumulator, 16, 16, 16, float> acc[2][4];
#pragma unroll
    for (int i = 0; i < 2; i++)
#pragma unroll
        for (int j = 0; j < 4; j++) wmma::fill_fragment(acc[i][j], 0.0f);

    auto issue_load = [&](int b, int kc) {
#pragma unroll
        for (int p = 0; p < 4; ++p) {
            int idx = p * 256 + tid;
            int row = idx >> 3, c8 = idx & 7;
            CP_ASYNC16(AsU[b] + (row * A_LDH + c8 * 8) * 2,
                       A + (size_t)(br * 128 + row) * lda + kc * 64 + c8 * 8);
        }
        if (B_KN) {
#pragma unroll
            for (int p = 0; p < 4; ++p) {
                int idx = p * 256 + tid;
                int row = idx >> 4, c8 = idx & 15;
                CP_ASYNC16(BsU[b] + (row * B_LDH_KN + c8 * 8) * 2,
                           B + (size_t)(kc * 64 + row) * ldb + bc * 128 + c8 * 8);
            }
        } else {
#pragma unroll
            for (int p = 0; p < 4; ++p) {
                int idx = p * 256 + tid;
                int row = idx >> 3, c8 = idx & 7;
                CP_ASYNC16(BsU[b] + (row * A_LDH + c8 * 8) * 2,
                           B + (size_t)(bc * 128 + row) * ldb + kc * 64 + c8 * 8);
            }
        }
        CP_COMMIT();
    };

    issue_load(0, 0);

    int cur = 0;
    for (int kc = 0; kc < kChunks; ++kc) {
        if (kc + 1 < kChunks) { issue_load(cur ^ 1, kc + 1); CP_WAIT(1); }
        else                  { CP_WAIT(0); }
        __syncthreads();

        const __half* Asb = AsH[cur];
        const __half* Bsb = BsH[cur];
#pragma unroll
        for (int ks = 0; ks < 4; ++ks) {
            const int k0 = ks * 16;
            wmma::fragment<wmma::matrix_a, 16, 16, 16, __half, wmma::row_major> af[2];
#pragma unroll
            for (int i = 0; i < 2; i++)
                wmma::load_matrix_sync(af[i], Asb + (wr * 32 + i * 16) * A_LDH + k0, A_LDH);
            if (B_KN) {
                wmma::fragment<wmma::matrix_b, 16, 16, 16, __half, wmma::row_major> bf[4];
#pragma unroll
                for (int j = 0; j < 4; j++)
                    wmma::load_matrix_sync(bf[j], Bsb + k0 * B_LDH_KN + wc * 64 + j * 16, B_LDH_KN);
#pragma unroll
                for (int i = 0; i < 2; i++)
#pragma unroll
                    for (int j = 0; j < 4; j++)
                        wmma::mma_sync(acc[i][j], af[i], bf[j], acc[i][j]);
            } else {
                wmma::fragment<wmma::matrix_b, 16, 16, 16, __half, wmma::col_major> bf[4];
#pragma unroll
                for (int j = 0; j < 4; j++)
                    wmma::load_matrix_sync(bf[j], Bsb + (wc * 64 + j * 16) * A_LDH + k0, A_LDH);
#pragma unroll
                for (int i = 0; i < 2; i++)
#pragma unroll
                    for (int j = 0; j < 4; j++)
                        wmma::mma_sync(acc[i][j], af[i], bf[j], acc[i][j]);
            }
        }
        __syncthreads();
        cur ^= 1;
    }

    if (!OUT_HALF) {
#pragma unroll
        for (int i = 0; i < 2; i++)
#pragma unroll
            for (int j = 0; j < 4; j++) {
#pragma unroll
                for (int t = 0; t < acc[i][j].num_elements; t++) acc[i][j].x[t] *= scale;
                float* cp = Cf + (size_t)(br * 128 + wr * 32 + i * 16) * ldc + bc * 128 + wc * 64 + j * 16;
                wmma::store_matrix_sync(cp, acc[i][j], ldc, wmma::mem_row_major);
            }
    } else {
        float* stg = (float*)smc;
#pragma unroll
        for (int i = 0; i < 2; i++)
#pragma unroll
            for (int j = 0; j < 4; j++)
                wmma::store_matrix_sync(stg + (size_t)(wr * 32 + i * 16) * STG_LD + wc * 64 + j * 16,
                                        acc[i][j], STG_LD, wmma::mem_row_major);
        __syncthreads();
        const int row = tid >> 1;
        const int cb = (tid & 1) * 64;
        const float* srow = stg + (size_t)row * STG_LD + cb;
        __half2* drow = (__half2*)(Ch + (size_t)(br * 128 + row) * ldc + bc * 128 + cb);
#pragma unroll
        for (int c = 0; c < 32; ++c)
            drow[c] = __floats2half2_rn(srow[2 * c], srow[2 * c + 1]);
    }
}

// ---------------------------------------------------------------------------
// Kernel 0: fused fp32 -> fp16 conversion. grid.y: 0=X, 1..3=W[q,k,v]
// ---------------------------------------------------------------------------
__global__ void __launch_bounds__(256)
f2h_all(const float* __restrict__ x, const float* __restrict__ wq,
        const float* __restrict__ wk, const float* __restrict__ wv)
{
    const int z = blockIdx.y;
    const float* s;
    __half* d;
    int n4;
    if (z == 0) { s = x;  d = g_Xh;    n4 = BSZ * TN * CN / 4; }
    else {
        n4 = CN * HN / 4;
        if (z == 1)      { s = wq; d = g_Wh[0]; }
        else if (z == 2) { s = wk; d = g_Wh[1]; }
        else             { s = wv; d = g_Wh[2]; }
    }
    int i = blockIdx.x * 256 + threadIdx.x;
    if (i < n4) {
        float4 v = *(const float4*)(s + (size_t)i * 4);
        __half2* o = (__half2*)(d + (size_t)i * 4);
        o[0] = __floats2half2_rn(v.x, v.y);
        o[1] = __floats2half2_rn(v.z, v.w);
    }
}

// ---------------------------------------------------------------------------
// Kernel 1: QKV projections. grid = (8, 64, 3). Wh = [C,H] -> B_KN, out half
// ---------------------------------------------------------------------------
__global__ void __launch_bounds__(256, 2)
qkv_h()
{
    __half* Out;
    if (blockIdx.z == 0)      Out = g_Qh;
    else if (blockIdx.z == 1) Out = g_Kh;
    else                      Out = g_Vh;
    wmma_tile_h<true, true>(g_Xh, CN, g_Wh[blockIdx.z], HN,
                            nullptr, Out, HN, CN / 64, blockIdx.y, blockIdx.x, 1.0f);
}

// ---------------------------------------------------------------------------
// Kernel 2: S = Qh Kh^T * scale. Compact lower-triangle launch:
// grid = (136, 1, BSZ); linear index -> (by, bx) with bx <= by.
// ---------------------------------------------------------------------------
__global__ void __launch_bounds__(256, 2)
scores_h()
{
    const int idx = blockIdx.x;
    int row = (int)((sqrtf(8.0f * idx + 1.0f) - 1.0f) * 0.5f);
    while ((row + 1) * (row + 2) / 2 <= idx) row++;
    while (row * (row + 1) / 2 > idx) row--;
    const int col = idx - row * (row + 1) / 2;

    const int b = blockIdx.z;
    const __half* Q = g_Qh + (size_t)b * TN * HN;
    const __half* K = g_Kh + (size_t)b * TN * HN;
    float* S = g_S + (size_t)b * TN * TN;
    wmma_tile_h<false, false>(Q, HN, K, HN, S, nullptr, TN, HN / 64,
                              row, col, 0.03125f);
}

// ---------------------------------------------------------------------------
// Kernel 3: causal softmax; reads fp32 S, writes fp16 P (padded). grid (TN,BSZ)
// exp computed ONCE, staged in smem, then normalized + converted.
// ---------------------------------------------------------------------------
__global__ void __launch_bounds__(256)
softmax_h()
{
    const int t = blockIdx.x;
    const int b = blockIdx.y;
    const float* row = g_S + ((size_t)b * TN + t) * TN;
    __half* prow = g_Ph + ((size_t)b * TN + t) * TN;
    const int n = t + 1;
    const int tid = threadIdx.x;

    __shared__ float ebuf[TN];
    __shared__ float red[8];

    float m = -INFINITY;
    for (int i = tid; i < n; i += 256) m = fmaxf(m, row[i]);
#pragma unroll
    for (int o = 16; o > 0; o >>= 1) m = fmaxf(m, __shfl_xor_sync(0xffffffffu, m, o));
    if ((tid & 31) == 0) red[tid >> 5] = m;
    __syncthreads();
    m = -INFINITY;
#pragma unroll
    for (int w = 0; w < 8; w++) m = fmaxf(m, red[w]);
    __syncthreads();

    float s = 0.f;
    for (int i = tid; i < n; i += 256) {
        float e = __expf(row[i] - m);
        ebuf[i] = e;
        s += e;
    }
#pragma unroll
    for (int o = 16; o > 0; o >>= 1) s += __shfl_xor_sync(0xffffffffu, s, o);
    if ((tid & 31) == 0) red[tid >> 5] = s;
    __syncthreads();
    s = 0.f;
#pragma unroll
    for (int w = 0; w < 8; w++) s += red[w];

    const float inv = 1.0f / s;
    for (int i = tid; i < n; i += 256) prow[i] = __float2half(ebuf[i] * inv);

    const int npad = ((t >> 7) + 1) << 7;
    for (int i = n + tid; i < npad; i += 256) prow[i] = __float2half(0.f);
}

// ---------------------------------------------------------------------------
// Kernel 4: O = Ph Vh, k truncated at diagonal. grid (8,16,BSZ). B_KN, fp32 out
// Heavy rows scheduled first (br reversed) to shrink the tail wave.
// ---------------------------------------------------------------------------
__global__ void __launch_bounds__(256, 2)
pv_h(float* __restrict__ out)
{
    const int b = blockIdx.z;
    const int br = (TN / 128 - 1) - blockIdx.y;   // 15..0, heavy first
    const __half* P = g_Ph + (size_t)b * TN * TN;
    const __half* V = g_Vh + (size_t)b * TN * HN;
    float* O = out + (size_t)b * TN * HN;
    const int kChunks = (br + 1) * 2;   // (br+1)*128 / 64
    wmma_tile_h<true, false>(P, TN, V, HN, O, nullptr, HN, kChunks,
                             br, blockIdx.x, 1.0f);
}

// ---------------------------------------------------------------------------
extern "C" void kernel_launch(void* const* d_in, const int* in_sizes, int n_in,
                              void* d_out, int out_size)
{
    const float* x  = (const float*)d_in[0];
    const float* Wk = (const float*)d_in[1];
    const float* Wq = (const float*)d_in[2];
    const float* Wv = (const float*)d_in[3];
    float* out = (float*)d_out;

    cudaFuncSetAttribute(qkv_h,    cudaFuncAttributeMaxDynamicSharedMemorySize, SMEM_BYTES);
    cudaFuncSetAttribute(scores_h, cudaFuncAttributeMaxDynamicSharedMemorySize, SMEM_BYTES);
    cudaFuncSetAttribute(pv_h,     cudaFuncAttributeMaxDynamicSharedMemorySize, SMEM_BYTES);

    const int nX4 = BSZ * TN * CN / 4;
    f2h_all<<<dim3((nX4 + 255) / 256, 4), 256>>>(x, Wq, Wk, Wv);

    qkv_h<<<dim3(HN / 128, (BSZ * TN) / 128, 3), 256, SMEM_BYTES>>>();
    const int nTri = (TN / 128) * (TN / 128 + 1) / 2;   // 136
    scores_h<<<dim3(nTri, 1, BSZ), 256, SMEM_BYTES>>>();
    softmax_h<<<dim3(TN, BSZ), 256>>>();
    pv_h<<<dim3(HN / 128, TN / 128, BSZ), 256, SMEM_BYTES>>>(out);
}